// round 2
// baseline (speedup 1.0000x reference)
#include <cuda_runtime.h>
#include <cuda_bf16.h>
#include <cstdint>

#define N_NODES 100000
#define N_EDGES 640000
#define HID 128
#define OUTD 64

// ---------------- scratch (device globals; no allocation allowed) ----------
__device__ __align__(16) float  g_sumx[N_NODES];
__device__ __align__(16) float  g_cnt [N_NODES];
__device__ __align__(16) float  g_A[HID * OUTD];   // W2l @ Wh1   [128,64]
__device__ __align__(16) float  g_B[HID * OUTD];   // W2r @ Wh1   [128,64]
__device__ __align__(16) float  g_c[OUTD];         // b2 @ Wh1 + bh1
__device__ __align__(16) float4 g_p  [N_NODES * OUTD / 4];  // h1 @ A       (scattered over edges)
__device__ __align__(16) float4 g_t  [N_NODES * OUTD / 4];  // h1 @ B + c   (per-node)
__device__ __align__(16) float4 g_agg[N_NODES * OUTD / 4];  // segment_sum(p[src])

// ---------------- zero scratch --------------------------------------------
__global__ void k_zero() {
    int i = blockIdx.x * blockDim.x + threadIdx.x;
    const int tot4 = N_NODES * OUTD / 4;
    float4 z = make_float4(0.f, 0.f, 0.f, 0.f);
    if (i < tot4) g_agg[i] = z;
    if (i < N_NODES) { g_sumx[i] = 0.f; g_cnt[i] = 0.f; }
}

// ---------------- layer-1 scalar aggregation ------------------------------
__global__ void k_edges(const float* __restrict__ x, const int* __restrict__ ei) {
    int e = blockIdx.x * blockDim.x + threadIdx.x;
    if (e >= N_EDGES) return;
    int s = ei[e];
    int d = ei[N_EDGES + e];
    atomicAdd(&g_sumx[d], x[s]);
    atomicAdd(&g_cnt[d], 1.0f);
}

// ---------------- fold head into layer-2 weights ---------------------------
// A = W2l @ Wh1, B = W2r @ Wh1, c = b2 @ Wh1 + bh1
__global__ void k_weights(const float* __restrict__ W2l, const float* __restrict__ W2r,
                          const float* __restrict__ b2,  const float* __restrict__ Wh1,
                          const float* __restrict__ bh1) {
    int j = threadIdx.x;     // 0..63
    int i = blockIdx.x;      // 0..128 (128 = bias row)
    if (i < HID) {
        float a = 0.f, b = 0.f;
        #pragma unroll 8
        for (int k = 0; k < HID; ++k) {
            float w = Wh1[k * OUTD + j];
            a += W2l[i * HID + k] * w;
            b += W2r[i * HID + k] * w;
        }
        g_A[i * OUTD + j] = a;
        g_B[i * OUTD + j] = b;
    } else {
        float cc = bh1[j];
        #pragma unroll 8
        for (int k = 0; k < HID; ++k) cc += b2[k] * Wh1[k * OUTD + j];
        g_c[j] = cc;
    }
}

// ---------------- per-node: build h1 on the fly, compute p = h1@A, t = h1@B + c
// Block: 256 threads handles 64 nodes. H staged in smem; A/B streamed via L1.
__global__ __launch_bounds__(256) void k_nodes(const float* __restrict__ x,
                                               const float* __restrict__ W1l,
                                               const float* __restrict__ W1r,
                                               const float* __restrict__ b1) {
    __shared__ float Hs[64][HID];     // 32 KB
    const int tid = threadIdx.x;
    const int n0  = blockIdx.x * 64;

    // phase 1: h1[n][k] = relu(m_n * W1l[k] + x_n * W1r[k] + b1[k])
    #pragma unroll
    for (int it = 0; it < 32; ++it) {
        int idx  = it * 256 + tid;        // 0..8191
        int n    = idx >> 7;
        int k    = idx & (HID - 1);
        int node = n0 + n;
        float h = 0.f;
        if (node < N_NODES) {
            float xv = x[node];
            float m  = g_sumx[node] / fmaxf(g_cnt[node], 1.0f);
            h = fmaxf(m * W1l[k] + xv * W1r[k] + b1[k], 0.f);
        }
        Hs[n][k] = h;
    }
    __syncthreads();

    // phase 2: each thread -> 8 nodes x 4 cols of the combined [A|B] (128 cols)
    const int cg = (tid & 31) * 4;          // 0..124
    const int ng = (tid >> 5) * 8;          // 0..56
    const float* Wmat = (cg < OUTD) ? (g_A + cg) : (g_B + (cg - OUTD));

    float acc[8][4];
    #pragma unroll
    for (int n = 0; n < 8; ++n)
        acc[n][0] = acc[n][1] = acc[n][2] = acc[n][3] = 0.f;

    #pragma unroll 4
    for (int k = 0; k < HID; ++k) {
        float4 w = *(const float4*)(Wmat + k * OUTD);
        #pragma unroll
        for (int n = 0; n < 8; ++n) {
            float h = Hs[ng + n][k];
            acc[n][0] += h * w.x;
            acc[n][1] += h * w.y;
            acc[n][2] += h * w.z;
            acc[n][3] += h * w.w;
        }
    }

    if (cg < OUTD) {
        #pragma unroll
        for (int n = 0; n < 8; ++n) {
            int node = n0 + ng + n;
            if (node < N_NODES)
                g_p[(node * OUTD + cg) >> 2] =
                    make_float4(acc[n][0], acc[n][1], acc[n][2], acc[n][3]);
        }
    } else {
        int c = cg - OUTD;
        float4 cc = *(const float4*)(g_c + c);
        #pragma unroll
        for (int n = 0; n < 8; ++n) {
            int node = n0 + ng + n;
            if (node < N_NODES)
                g_t[(node * OUTD + c) >> 2] =
                    make_float4(acc[n][0] + cc.x, acc[n][1] + cc.y,
                                acc[n][2] + cc.z, acc[n][3] + cc.w);
        }
    }
}

// ---------------- edge scatter: agg[dst] += p[src]  (64-dim, vector red) ---
__global__ void k_scatter(const int* __restrict__ ei) {
    long long t = (long long)blockIdx.x * blockDim.x + threadIdx.x;
    if (t >= (long long)N_EDGES * 16) return;
    int e = (int)(t >> 4);
    int q = (int)(t & 15);
    int s = ei[e];
    int d = ei[N_EDGES + e];
    float4 v = g_p[s * (OUTD / 4) + q];
    float* addr = (float*)&g_agg[d * (OUTD / 4) + q];
    asm volatile("red.global.add.v4.f32 [%0], {%1,%2,%3,%4};"
                 :: "l"(addr), "f"(v.x), "f"(v.y), "f"(v.z), "f"(v.w)
                 : "memory");
}

// ---------------- epilogue: z = relu(agg/maxc + t); out = sigmoid(z.Wh2 + bh2)
__global__ void k_out(const float* __restrict__ Wh2, const float* __restrict__ bh2,
                      float* __restrict__ out) {
    int gtid = blockIdx.x * blockDim.x + threadIdx.x;
    int node = gtid >> 5;
    int lane = gtid & 31;
    if (node >= N_NODES) return;
    float inv = 1.0f / fmaxf(g_cnt[node], 1.0f);
    const float* aggp = (const float*)&g_agg[node * (OUTD / 4)];
    const float* tp   = (const float*)&g_t  [node * (OUTD / 4)];
    float acc = 0.f;
    #pragma unroll
    for (int c0 = 0; c0 < OUTD; c0 += 32) {
        int c = c0 + lane;
        float z = fmaxf(aggp[c] * inv + tp[c], 0.f);
        acc += z * Wh2[c];
    }
    #pragma unroll
    for (int o = 16; o; o >>= 1) acc += __shfl_xor_sync(0xffffffffu, acc, o);
    if (lane == 0) out[node] = 1.0f / (1.0f + __expf(-(acc + bh2[0])));
}

// ---------------------------------------------------------------------------
extern "C" void kernel_launch(void* const* d_in, const int* in_sizes, int n_in,
                              void* d_out, int out_size) {
    const float* x   = (const float*)d_in[0];
    const int*   ei  = (const int*)  d_in[1];
    const float* W1l = (const float*)d_in[2];
    const float* W1r = (const float*)d_in[3];
    const float* b1  = (const float*)d_in[4];
    const float* W2l = (const float*)d_in[5];
    const float* W2r = (const float*)d_in[6];
    const float* b2  = (const float*)d_in[7];
    const float* Wh1 = (const float*)d_in[8];
    const float* bh1 = (const float*)d_in[9];
    const float* Wh2 = (const float*)d_in[10];
    const float* bh2 = (const float*)d_in[11];
    float* out = (float*)d_out;

    int zero_threads = N_NODES * OUTD / 4;
    k_zero   <<<(zero_threads + 255) / 256, 256>>>();
    k_edges  <<<(N_EDGES + 255) / 256, 256>>>(x, ei);
    k_weights<<<HID + 1, OUTD>>>(W2l, W2r, b2, Wh1, bh1);
    k_nodes  <<<(N_NODES + 63) / 64, 256>>>(x, W1l, W1r, b1);
    long long sc = (long long)N_EDGES * 16;
    k_scatter<<<(unsigned)((sc + 255) / 256), 256>>>(ei);
    k_out    <<<(N_NODES * 32 + 255) / 256, 256>>>(Wh2, bh2, out);
}

// round 5
// speedup vs baseline: 1.2531x; 1.2531x over previous
#include <cuda_runtime.h>
#include <cuda_bf16.h>
#include <cstdint>

#define N_NODES 100000
#define N_EDGES 640000
#define HID 128
#define OUTD 64

// ---------------- scratch (device globals; no allocation allowed) ----------
__device__ __align__(16) float  g_sumx[N_NODES];
__device__ __align__(16) float  g_cnt [N_NODES];
__device__ __align__(16) float  g_A[HID * OUTD];   // W2l @ Wh1   [128,64]
__device__ __align__(16) float  g_B[HID * OUTD];   // W2r @ Wh1   [128,64]
__device__ __align__(16) float  g_c[OUTD];         // b2 @ Wh1 + bh1
__device__ __align__(16) float4 g_p  [N_NODES * OUTD / 4];  // h1 @ A       (scattered over edges)
__device__ __align__(16) float4 g_t  [N_NODES * OUTD / 4];  // h1 @ B + c   (per-node)
__device__ __align__(16) float4 g_agg[N_NODES * OUTD / 4];  // segment_sum(p[src])

// ---------------- zero scratch --------------------------------------------
__global__ void k_zero() {
    int i = blockIdx.x * blockDim.x + threadIdx.x;
    const int tot4 = N_NODES * OUTD / 4;
    float4 z = make_float4(0.f, 0.f, 0.f, 0.f);
    if (i < tot4) g_agg[i] = z;
    if (i < N_NODES) { g_sumx[i] = 0.f; g_cnt[i] = 0.f; }
}

// ---------------- layer-1 scalar aggregation ------------------------------
__global__ void k_edges(const float* __restrict__ x, const int* __restrict__ ei) {
    int e = blockIdx.x * blockDim.x + threadIdx.x;
    if (e >= N_EDGES) return;
    int s = ei[e];
    int d = ei[N_EDGES + e];
    atomicAdd(&g_sumx[d], x[s]);
    atomicAdd(&g_cnt[d], 1.0f);
}

// ---------------- fold head into layer-2 weights ---------------------------
// A = W2l @ Wh1, B = W2r @ Wh1, c = b2 @ Wh1 + bh1
__global__ void k_weights(const float* __restrict__ W2l, const float* __restrict__ W2r,
                          const float* __restrict__ b2,  const float* __restrict__ Wh1,
                          const float* __restrict__ bh1) {
    int j = threadIdx.x;     // 0..63
    int i = blockIdx.x;      // 0..128 (128 = bias row)
    if (i < HID) {
        float a = 0.f, b = 0.f;
        #pragma unroll 8
        for (int k = 0; k < HID; ++k) {
            float w = Wh1[k * OUTD + j];
            a += W2l[i * HID + k] * w;
            b += W2r[i * HID + k] * w;
        }
        g_A[i * OUTD + j] = a;
        g_B[i * OUTD + j] = b;
    } else {
        float cc = bh1[j];
        #pragma unroll 8
        for (int k = 0; k < HID; ++k) cc += b2[k] * Wh1[k * OUTD + j];
        g_c[j] = cc;
    }
}

// ---------------- per-node GEMM, f32x2-packed over the node dimension ------
// Block: 256 threads handles 64 nodes. Hs stored k-major so node pairs are
// one LDS.64. Inner loop uses fma.rn.f32x2 (FFMA2): 2 FMAs per instruction.
__global__ __launch_bounds__(256) void k_nodes(const float* __restrict__ x,
                                               const float* __restrict__ W1l,
                                               const float* __restrict__ W1r,
                                               const float* __restrict__ b1) {
    __shared__ float Hs[HID][64];      // 32 KB, k-major
    __shared__ float mn[64], xn[64];
    const int tid = threadIdx.x;
    const int n0  = blockIdx.x * 64;

    // stage 0: per-node scalars
    if (tid < 64) {
        int node = n0 + tid;
        float xv = 0.f, m = 0.f;
        if (node < N_NODES) {
            xv = x[node];
            m  = g_sumx[node] / fmaxf(g_cnt[node], 1.0f);
        }
        mn[tid] = m; xn[tid] = xv;
    }
    __syncthreads();

    // phase 1: Hs[k][n] = relu(m_n*W1l[k] + x_n*W1r[k] + b1[k])
    #pragma unroll
    for (int it = 0; it < 32; ++it) {
        int idx = it * 256 + tid;       // 0..8191
        int k   = idx >> 6;
        int n   = idx & 63;
        Hs[k][n] = fmaxf(mn[n] * W1l[k] + xn[n] * W1r[k] + b1[k], 0.f);
    }
    __syncthreads();

    // phase 2: warp w handles nodes ng..ng+7; lane handles 4 cols of [A|B].
    const int lane = tid & 31;
    const int wrp  = tid >> 5;
    const int cg   = lane * 4;          // 0..124 over combined 128 cols
    const int ng   = wrp * 8;
    const float* Wmat = (cg < OUTD) ? (g_A + cg) : (g_B + (cg - OUTD));

    // acc2[np][c]: packed pair (node ng+2np, ng+2np+1), column c
    unsigned long long acc2[4][4];
    #pragma unroll
    for (int np = 0; np < 4; ++np)
        #pragma unroll
        for (int c = 0; c < 4; ++c) acc2[np][c] = 0ull;

    #pragma unroll 4
    for (int k = 0; k < HID; ++k) {
        float4 wv = *(const float4*)(Wmat + k * OUTD);
        unsigned long long wd[4];
        asm("mov.b64 %0,{%1,%1};" : "=l"(wd[0]) : "f"(wv.x));
        asm("mov.b64 %0,{%1,%1};" : "=l"(wd[1]) : "f"(wv.y));
        asm("mov.b64 %0,{%1,%1};" : "=l"(wd[2]) : "f"(wv.z));
        asm("mov.b64 %0,{%1,%1};" : "=l"(wd[3]) : "f"(wv.w));
        const unsigned long long* hrow = (const unsigned long long*)&Hs[k][ng];
        #pragma unroll
        for (int np = 0; np < 4; ++np) {
            unsigned long long h2 = hrow[np];
            asm("fma.rn.f32x2 %0,%1,%2,%0;" : "+l"(acc2[np][0]) : "l"(h2), "l"(wd[0]));
            asm("fma.rn.f32x2 %0,%1,%2,%0;" : "+l"(acc2[np][1]) : "l"(h2), "l"(wd[1]));
            asm("fma.rn.f32x2 %0,%1,%2,%0;" : "+l"(acc2[np][2]) : "l"(h2), "l"(wd[2]));
            asm("fma.rn.f32x2 %0,%1,%2,%0;" : "+l"(acc2[np][3]) : "l"(h2), "l"(wd[3]));
        }
    }

    // unpack + store
    if (cg < OUTD) {
        #pragma unroll
        for (int np = 0; np < 4; ++np) {
            float lo[4], hi[4];
            #pragma unroll
            for (int c = 0; c < 4; ++c)
                asm("mov.b64 {%0,%1},%2;" : "=f"(lo[c]), "=f"(hi[c]) : "l"(acc2[np][c]));
            int node0 = n0 + ng + 2 * np;
            if (node0 < N_NODES)
                g_p[node0 * (OUTD / 4) + (cg >> 2)] = make_float4(lo[0], lo[1], lo[2], lo[3]);
            if (node0 + 1 < N_NODES)
                g_p[(node0 + 1) * (OUTD / 4) + (cg >> 2)] = make_float4(hi[0], hi[1], hi[2], hi[3]);
        }
    } else {
        int c0 = cg - OUTD;
        float4 cc = *(const float4*)(g_c + c0);
        #pragma unroll
        for (int np = 0; np < 4; ++np) {
            float lo[4], hi[4];
            #pragma unroll
            for (int c = 0; c < 4; ++c)
                asm("mov.b64 {%0,%1},%2;" : "=f"(lo[c]), "=f"(hi[c]) : "l"(acc2[np][c]));
            int node0 = n0 + ng + 2 * np;
            if (node0 < N_NODES)
                g_t[node0 * (OUTD / 4) + (c0 >> 2)] =
                    make_float4(lo[0] + cc.x, lo[1] + cc.y, lo[2] + cc.z, lo[3] + cc.w);
            if (node0 + 1 < N_NODES)
                g_t[(node0 + 1) * (OUTD / 4) + (c0 >> 2)] =
                    make_float4(hi[0] + cc.x, hi[1] + cc.y, hi[2] + cc.z, hi[3] + cc.w);
        }
    }
}

// ---------------- edge scatter: agg[dst] += p[src]  (64-dim, vector red) ---
__global__ void k_scatter(const int* __restrict__ ei) {
    long long t = (long long)blockIdx.x * blockDim.x + threadIdx.x;
    if (t >= (long long)N_EDGES * 16) return;
    int e = (int)(t >> 4);
    int q = (int)(t & 15);
    int s = ei[e];
    int d = ei[N_EDGES + e];
    float4 v = g_p[s * (OUTD / 4) + q];
    float* addr = (float*)&g_agg[d * (OUTD / 4) + q];
    asm volatile("red.global.add.v4.f32 [%0], {%1,%2,%3,%4};"
                 :: "l"(addr), "f"(v.x), "f"(v.y), "f"(v.z), "f"(v.w)
                 : "memory");
}

// ---------------- epilogue: z = relu(agg/maxc + t); out = sigmoid(z.Wh2 + bh2)
__global__ void k_out(const float* __restrict__ Wh2, const float* __restrict__ bh2,
                      float* __restrict__ out) {
    int gtid = blockIdx.x * blockDim.x + threadIdx.x;
    int node = gtid >> 5;
    int lane = gtid & 31;
    if (node >= N_NODES) return;
    float inv = 1.0f / fmaxf(g_cnt[node], 1.0f);
    const float* aggp = (const float*)&g_agg[node * (OUTD / 4)];
    const float* tp   = (const float*)&g_t  [node * (OUTD / 4)];
    float acc = 0.f;
    #pragma unroll
    for (int c0 = 0; c0 < OUTD; c0 += 32) {
        int c = c0 + lane;
        float z = fmaxf(aggp[c] * inv + tp[c], 0.f);
        acc += z * Wh2[c];
    }
    #pragma unroll
    for (int o = 16; o; o >>= 1) acc += __shfl_xor_sync(0xffffffffu, acc, o);
    if (lane == 0) out[node] = 1.0f / (1.0f + __expf(-(acc + bh2[0])));
}

// ---------------------------------------------------------------------------
extern "C" void kernel_launch(void* const* d_in, const int* in_sizes, int n_in,
                              void* d_out, int out_size) {
    const float* x   = (const float*)d_in[0];
    const int*   ei  = (const int*)  d_in[1];
    const float* W1l = (const float*)d_in[2];
    const float* W1r = (const float*)d_in[3];
    const float* b1  = (const float*)d_in[4];
    const float* W2l = (const float*)d_in[5];
    const float* W2r = (const float*)d_in[6];
    const float* b2  = (const float*)d_in[7];
    const float* Wh1 = (const float*)d_in[8];
    const float* bh1 = (const float*)d_in[9];
    const float* Wh2 = (const float*)d_in[10];
    const float* bh2 = (const float*)d_in[11];
    float* out = (float*)d_out;

    int zero_threads = N_NODES * OUTD / 4;
    k_zero   <<<(zero_threads + 255) / 256, 256>>>();
    k_edges  <<<(N_EDGES + 255) / 256, 256>>>(x, ei);
    k_weights<<<HID + 1, OUTD>>>(W2l, W2r, b2, Wh1, bh1);
    k_nodes  <<<(N_NODES + 63) / 64, 256>>>(x, W1l, W1r, b1);
    long long sc = (long long)N_EDGES * 16;
    k_scatter<<<(unsigned)((sc + 255) / 256), 256>>>(ei);
    k_out    <<<(N_NODES * 32 + 255) / 256, 256>>>(Wh2, bh2, out);
}